// round 1
// baseline (speedup 1.0000x reference)
#include <cuda_runtime.h>
#include <cstddef>

// ---------------------------------------------------------------------------
// Problem constants
// ---------------------------------------------------------------------------
constexpr int B_  = 2;
constexpr int C_  = 64;
constexpr int C4_ = 256;
constexpr int H_  = 64;
constexpr int W_  = 96;
constexpr int HW_ = H_ * W_;

// Scratch (device globals: no allocations allowed)
__device__ float g_t1[(size_t)B_ * C4_ * HW_];
__device__ float g_t2[(size_t)B_ * C4_ * HW_];
__device__ float g_Q [(size_t)B_ * C_  * HW_];
__device__ float g_K [(size_t)B_ * C_  * HW_];

// ---------------------------------------------------------------------------
// Grouped 3x3 conv (groups=4, in=out=256ch), stride 1, pad 1.
// MODE 1: input = BN(catfea) applied on load; output = leaky(conv + bias)
// MODE 2: input = t1 (raw);  output = conv + bias + BN(catfea) (residual)
// Tile: 8 rows x 32 cols, 64 out channels per block. 256 threads,
// each thread computes 8 oc x 8 px.
// ---------------------------------------------------------------------------
constexpr int TH   = 8;
constexpr int TW   = 32;
constexpr int ICB  = 8;
constexpr int INROW   = TW + 2;   // 34 valid cols
constexpr int INPITCH = 35;       // padded pitch (conflict-free)

template <int MODE>
__global__ __launch_bounds__(256)
void conv3x3_kernel(const float* __restrict__ in,
                    const float* __restrict__ cat,
                    const float* __restrict__ wgt,   // (256, 64, 3, 3)
                    const float* __restrict__ bias,  // (256)
                    const float* __restrict__ bn_g,
                    const float* __restrict__ bn_b,
                    const float* __restrict__ bn_m,
                    const float* __restrict__ bn_v,
                    float* __restrict__ out)
{
    __shared__ float s_in[ICB * (TH + 2) * INPITCH];
    __shared__ float s_w[ICB * 64 * 9];
    __shared__ float s_sc[64];
    __shared__ float s_sh[64];

    const int tid = threadIdx.x;
    const int bz  = blockIdx.z;        // b*4 + g
    const int b   = bz >> 2;
    const int g   = bz & 3;
    const int y0  = blockIdx.y * TH;
    const int x0  = blockIdx.x * TW;
    const int chbase = g * 64;

    if (tid < 64) {
        const int ch = chbase + tid;
        const float sc = bn_g[ch] * rsqrtf(bn_v[ch] + 1e-5f);
        s_sc[tid] = sc;
        s_sh[tid] = bn_b[ch] - bn_m[ch] * sc;
    }

    // thread mapping: og (out-channel octet), p -> (rowp, colp)
    const int og   = tid >> 5;        // 0..7
    const int p    = tid & 31;
    const int rowp = p >> 2;          // 0..7
    const int colp = (p & 3) * 8;     // 0,8,16,24

    float acc[8][8];
#pragma unroll
    for (int o = 0; o < 8; o++)
#pragma unroll
        for (int q = 0; q < 8; q++) acc[o][q] = 0.f;

    const float* inb = in + (size_t)(b * C4_ + chbase) * HW_;

    __syncthreads();  // s_sc/s_sh ready

    for (int icb = 0; icb < 64; icb += ICB) {
        // stage input tile (with BN for MODE 1)
        for (int idx = tid; idx < ICB * (TH + 2) * INROW; idx += 256) {
            const int c   = idx / ((TH + 2) * INROW);
            const int rem = idx % ((TH + 2) * INROW);
            const int r   = rem / INROW;
            const int cc  = rem % INROW;
            const int gy  = y0 - 1 + r;
            const int gx  = x0 - 1 + cc;
            float v = 0.f;
            if ((unsigned)gy < (unsigned)H_ && (unsigned)gx < (unsigned)W_) {
                v = inb[(size_t)(icb + c) * HW_ + gy * W_ + gx];
                if (MODE == 1) v = v * s_sc[icb + c] + s_sh[icb + c];
            }
            s_in[(c * (TH + 2) + r) * INPITCH + cc] = v;
        }
        // stage weights: s_w[c*576 + oc*9 + t]
        for (int idx = tid; idx < ICB * 64 * 9; idx += 256) {
            const int c   = idx / 576;
            const int rem = idx % 576;
            const int oc  = rem / 9;
            const int t   = rem % 9;
            s_w[idx] = wgt[(size_t)(chbase + oc) * (64 * 9) + (icb + c) * 9 + t];
        }
        __syncthreads();

#pragma unroll 2
        for (int c = 0; c < ICB; c++) {
            float xv[3][10];
#pragma unroll
            for (int kh = 0; kh < 3; kh++)
#pragma unroll
                for (int t = 0; t < 10; t++)
                    xv[kh][t] = s_in[(c * (TH + 2) + rowp + kh) * INPITCH + colp + t];

#pragma unroll
            for (int o = 0; o < 8; o++) {
                const float* wp = &s_w[c * 576 + (og * 8 + o) * 9];
                const float w0 = wp[0], w1 = wp[1], w2 = wp[2];
                const float w3 = wp[3], w4 = wp[4], w5 = wp[5];
                const float w6 = wp[6], w7 = wp[7], w8 = wp[8];
#pragma unroll
                for (int q = 0; q < 8; q++) {
                    float s = acc[o][q];
                    s += w0 * xv[0][q] + w1 * xv[0][q + 1] + w2 * xv[0][q + 2];
                    s += w3 * xv[1][q] + w4 * xv[1][q + 1] + w5 * xv[1][q + 2];
                    s += w6 * xv[2][q] + w7 * xv[2][q + 1] + w8 * xv[2][q + 2];
                    acc[o][q] = s;
                }
            }
        }
        __syncthreads();
    }

    // epilogue
    const float* catb = cat + (size_t)(b * C4_ + chbase) * HW_;
    float*       outb = out + (size_t)(b * C4_ + chbase) * HW_;
    const int y = y0 + rowp;
#pragma unroll
    for (int o = 0; o < 8; o++) {
        const int oc = og * 8 + o;
        const float bv = bias[chbase + oc];
#pragma unroll
        for (int q = 0; q < 8; q++) {
            const int x = x0 + colp + q;
            float v = acc[o][q] + bv;
            if (MODE == 1) {
                v = (v > 0.f) ? v : 0.1f * v;         // LeakyReLU(0.1)
            } else {
                const float cv = catb[(size_t)oc * HW_ + y * W_ + x];
                v += cv * s_sc[oc] + s_sh[oc];        // + BN(catfea) residual
            }
            outb[(size_t)oc * HW_ + y * W_ + x] = v;
        }
    }
}

// ---------------------------------------------------------------------------
// Grouped 1x1 conv: (64 out, 256 in, groups=4). One thread per output elem.
// ---------------------------------------------------------------------------
__global__ __launch_bounds__(256)
void conv1x1_kernel(const float* __restrict__ in,    // (B, 256, H, W)
                    const float* __restrict__ wgt,   // (64, 64)
                    const float* __restrict__ bias,  // (64)
                    float* __restrict__ out)         // (B, 64, H, W)
{
    const int idx = blockIdx.x * blockDim.x + threadIdx.x;
    if (idx >= B_ * C_ * HW_) return;
    const int pix = idx % HW_;
    const int o   = (idx / HW_) % C_;
    const int b   = idx / (C_ * HW_);
    const int gin = (o >> 4) * 64;   // group = o/16, input channels g*64..
    const float* ip = in + (size_t)(b * C4_ + gin) * HW_ + pix;
    const float* wp = wgt + o * 64;
    float accv = bias[o];
#pragma unroll 16
    for (int ic = 0; ic < 64; ic++)
        accv += __ldg(wp + ic) * __ldg(ip + (size_t)ic * HW_);
    out[idx] = accv;
}

// ---------------------------------------------------------------------------
// Attention kernel. One block per (row i, batch b). 256 threads.
// Window centers per pixel from d_left/d_right; 8x8 windows; softmax over 64.
// Mean-subtraction of patches is dropped (softmax-invariant).
// ---------------------------------------------------------------------------
constexpr int WIN_F = 32 * 769;   // 32 ch chunk, 8 rows * 96 cols, pitch 769
constexpr int CEN_F = 32 * 96;
constexpr int M_F   = 96 * 65;    // 96 pixels x 64 taps, pitch 65
constexpr int SMEM_FLOATS = WIN_F + CEN_F + 2 * M_F + 6 * 96;
constexpr int SMEM_BYTES  = SMEM_FLOATS * 4;

__device__ __forceinline__
void load_win(const float* __restrict__ src, float* s_win, int b, int i, int c0, int tid)
{
    const float* sb = src + (size_t)(b * C_ + c0) * HW_;
    for (int idx = tid; idx < 32 * 768; idx += 256) {
        const int c   = idx / 768;
        const int rem = idx - c * 768;       // a*96 + col
        const int a   = rem / 96;
        const int col = rem - a * 96;
        const int gy  = i - 4 + a;
        float v = ((unsigned)gy < (unsigned)H_)
                      ? sb[(size_t)c * HW_ + gy * W_ + col] : 0.f;
        s_win[c * 769 + rem] = v;
    }
}

__device__ __forceinline__
void logits_pass(const float* __restrict__ winsrc, const float* __restrict__ censrc,
                 const int* s_ctr, float* Mtgt,
                 float* s_win, float* s_cen, int b, int i, int tid)
{
    for (int cb = 0; cb < 2; cb++) {
        const int c0 = cb * 32;
        load_win(winsrc, s_win, b, i, c0, tid);
        {
            const float* sb = censrc + (size_t)(b * C_ + c0) * HW_ + (size_t)i * W_;
            for (int idx = tid; idx < 32 * 96; idx += 256) {
                const int c = idx / 96, j = idx - c * 96;
                s_cen[c * 96 + j] = sb[(size_t)c * HW_ + j];
            }
        }
        __syncthreads();

        if (tid < 192) {
            const int j    = tid >> 1;
            const int koff = (tid & 1) * 32;
            const int cc   = s_ctr[j];
            float av[32];
#pragma unroll
            for (int kk = 0; kk < 32; kk++) av[kk] = 0.f;
            for (int c = 0; c < 32; c++) {
                const float qv = s_cen[c * 96 + j];
                const float* wb = s_win + c * 769;
#pragma unroll
                for (int kk = 0; kk < 32; kk++) {
                    const int k   = koff + kk;
                    const int a   = k >> 3;
                    const int dw  = k & 7;
                    const int col = cc - 4 + dw;
                    const float wv = ((unsigned)col < 96u) ? wb[a * 96 + col] : 0.f;
                    av[kk] += qv * wv;
                }
            }
            float* Mrow = Mtgt + j * 65 + koff;
#pragma unroll
            for (int kk = 0; kk < 32; kk++) Mrow[kk] += av[kk];
        }
        __syncthreads();
    }
}

__device__ __forceinline__
void softmax_row(float* row, int valid)
{
    if (!valid) {
#pragma unroll
        for (int k = 0; k < 64; k++) row[k] = 1.f / 64.f;
        return;
    }
    float mx = row[0];
#pragma unroll
    for (int k = 1; k < 64; k++) mx = fmaxf(mx, row[k]);
    float s = 0.f;
#pragma unroll
    for (int k = 0; k < 64; k++) { const float e = __expf(row[k] - mx); row[k] = e; s += e; }
    const float inv = 1.f / s;
#pragma unroll
    for (int k = 0; k < 64; k++) row[k] *= inv;
}

__device__ __forceinline__
void value_pass(const float* __restrict__ valsrc, const float* __restrict__ basesrc,
                float* __restrict__ outdst,
                const int* s_cr, const int* s_vR, const float* maskarr,
                const float* Mwt, float* s_win, int b, int i, int tid)
{
    for (int cb = 0; cb < 2; cb++) {
        const int c0 = cb * 32;
        load_win(valsrc, s_win, b, i, c0, tid);
        __syncthreads();

        const int clocal = tid & 31;
        const int jb     = tid >> 5;          // 0..7
        const float* wb  = s_win + clocal * 769;
        const int ch     = c0 + clocal;
        for (int m = 0; m < 12; m++) {
            const int j = jb + 8 * m;
            float accv = 0.f;
            if (s_vR[j]) {
                const int cc = s_cr[j];
                const float* Mrow = Mwt + j * 65;
#pragma unroll
                for (int k = 0; k < 64; k++) {
                    const int a   = k >> 3;
                    const int dw  = k & 7;
                    const int col = cc - 4 + dw;
                    const float wv = ((unsigned)col < 96u) ? wb[a * 96 + col] : 0.f;
                    accv += Mrow[k] * wv;
                }
            }
            const size_t gidx = ((size_t)(b * C_ + ch) * H_ + i) * W_ + j;
            outdst[gidx] = basesrc[gidx] + accv * maskarr[j];
        }
        __syncthreads();
    }
}

__global__ __launch_bounds__(256)
void attention_kernel(const float* __restrict__ Qf, const float* __restrict__ Kf,
                      const float* __restrict__ xL, const float* __restrict__ xR,
                      const int* __restrict__ dL, const int* __restrict__ dR,
                      float* __restrict__ outL, float* __restrict__ outR)
{
    extern __shared__ float smem[];
    float* s_win = smem;                         // WIN_F
    float* s_cen = s_win + WIN_F;                // CEN_F
    float* s_Mr  = s_cen + CEN_F;                // M_F
    float* s_Ml  = s_Mr + M_F;                   // M_F
    int*   s_cr  = (int*)(s_Ml + M_F);           // 96
    int*   s_cl  = s_cr + 96;                    // 96
    int*   s_vR  = s_cl + 96;                    // 96
    int*   s_vL  = s_vR + 96;                    // 96
    float* s_mL  = (float*)(s_vL + 96);          // 96 (V_left)
    float* s_mR  = s_mL + 96;                    // 96 (V_right)

    const int i = blockIdx.x;
    const int b = blockIdx.y;
    const int tid = threadIdx.x;

    if (tid < 96) {
        const int j = tid;
        const int dl = dL[(b * H_ + i) * W_ + j];
        const int dr = dR[(b * H_ + i) * W_ + j];
        const int cr = max(j - dl, 0);
        const int cl = min(j + dr, W_ - 1);
        s_cr[j] = cr;
        s_cl[j] = cl;
        const int rowok = (i + 4) < H_;
        s_vR[j] = (rowok && cr < W_ - 4) ? 1 : 0;
        s_vL[j] = (rowok && cl < W_ - 4) ? 1 : 0;
        s_mL[j] = (j - dl >= 0) ? 1.f : 0.f;
        s_mR[j] = (j + dr <= W_ - 1) ? 1.f : 0.f;
    }
    for (int idx = tid; idx < 2 * M_F; idx += 256) s_Mr[idx] = 0.f;
    __syncthreads();

    // logits r2l: window = K patches at cr, center = Q
    logits_pass(Kf, Qf, s_cr, s_Mr, s_win, s_cen, b, i, tid);
    // logits l2r: window = Q patches at cl, center = K
    logits_pass(Qf, Kf, s_cl, s_Ml, s_win, s_cen, b, i, tid);

    if (tid < 96) {
        softmax_row(s_Mr + tid * 65, s_vR[tid]);
        softmax_row(s_Ml + tid * 65, s_vL[tid]);
    }
    __syncthreads();

    // values (both use r2l coords, matching the source)
    value_pass(xR, xL, outL, s_cr, s_vR, s_mL, s_Mr, s_win, b, i, tid);
    value_pass(xL, xR, outR, s_cr, s_vR, s_mR, s_Ml, s_win, b, i, tid);
}

// ---------------------------------------------------------------------------
// Host launcher
// ---------------------------------------------------------------------------
extern "C" void kernel_launch(void* const* d_in, const int* in_sizes, int n_in,
                              void* d_out, int out_size)
{
    const float *xL, *xR, *catL, *catR;
    const float *bng, *bnb, *bnm, *bnv, *w1, *b1, *w2, *b2, *bqw, *bqb, *bsw, *bsb;
    const int *dL, *dR;

    const bool dict_order = (n_in >= 18) && (in_sizes[4] == B_ * H_ * W_);
    if (dict_order) {
        xL   = (const float*)d_in[0];  xR   = (const float*)d_in[1];
        catL = (const float*)d_in[2];  catR = (const float*)d_in[3];
        dL   = (const int*)  d_in[4];  dR   = (const int*)  d_in[5];
        bng  = (const float*)d_in[6];  bnb  = (const float*)d_in[7];
        bnm  = (const float*)d_in[8];  bnv  = (const float*)d_in[9];
        w1   = (const float*)d_in[10]; b1   = (const float*)d_in[11];
        w2   = (const float*)d_in[12]; b2   = (const float*)d_in[13];
        bqw  = (const float*)d_in[14]; bqb  = (const float*)d_in[15];
        bsw  = (const float*)d_in[16]; bsb  = (const float*)d_in[17];
    } else {
        xL   = (const float*)d_in[0];  xR   = (const float*)d_in[1];
        catL = (const float*)d_in[2];  catR = (const float*)d_in[3];
        bng  = (const float*)d_in[4];  bnb  = (const float*)d_in[5];
        bnm  = (const float*)d_in[6];  bnv  = (const float*)d_in[7];
        w1   = (const float*)d_in[8];  b1   = (const float*)d_in[9];
        w2   = (const float*)d_in[10]; b2   = (const float*)d_in[11];
        bqw  = (const float*)d_in[12]; bqb  = (const float*)d_in[13];
        bsw  = (const float*)d_in[14]; bsb  = (const float*)d_in[15];
        dL   = (const int*)  d_in[16]; dR   = (const int*)  d_in[17];
    }

    float *t1, *t2, *Qb, *Kb;
    cudaGetSymbolAddress((void**)&t1, g_t1);
    cudaGetSymbolAddress((void**)&t2, g_t2);
    cudaGetSymbolAddress((void**)&Qb, g_Q);
    cudaGetSymbolAddress((void**)&Kb, g_K);

    const dim3 cgrid(W_ / TW, H_ / TH, B_ * 4);   // (3, 8, 8)
    const int npix = B_ * C_ * HW_;

    // Left branch -> Q
    conv3x3_kernel<1><<<cgrid, 256>>>(catL, catL, w1, b1, bng, bnb, bnm, bnv, t1);
    conv3x3_kernel<2><<<cgrid, 256>>>(t1,   catL, w2, b2, bng, bnb, bnm, bnv, t2);
    conv1x1_kernel<<<(npix + 255) / 256, 256>>>(t2, bqw, bqb, Qb);
    // Right branch -> K
    conv3x3_kernel<1><<<cgrid, 256>>>(catR, catR, w1, b1, bng, bnb, bnm, bnv, t1);
    conv3x3_kernel<2><<<cgrid, 256>>>(t1,   catR, w2, b2, bng, bnb, bnm, bnv, t2);
    conv1x1_kernel<<<(npix + 255) / 256, 256>>>(t2, bsw, bsb, Kb);

    // Attention + outputs
    cudaFuncSetAttribute(attention_kernel,
                         cudaFuncAttributeMaxDynamicSharedMemorySize, SMEM_BYTES);
    float* outL = (float*)d_out;
    float* outR = outL + (size_t)B_ * C_ * HW_;
    attention_kernel<<<dim3(H_, B_), 256, SMEM_BYTES>>>(Qb, Kb, xL, xR, dL, dR, outL, outR);
}

// round 2
// speedup vs baseline: 1.3774x; 1.3774x over previous
#include <cuda_runtime.h>
#include <cstddef>

// ---------------------------------------------------------------------------
// Problem constants
// ---------------------------------------------------------------------------
constexpr int B_  = 2;
constexpr int C_  = 64;
constexpr int C4_ = 256;
constexpr int H_  = 64;
constexpr int W_  = 96;
constexpr int HW_ = H_ * W_;
constexpr int NSB = 2 * B_;   // side * batch slots

// Scratch (device globals: no allocations allowed). Layout [side*B+b][C4][HW]
__device__ float g_t1[(size_t)NSB * C4_ * HW_];
__device__ float g_t2[(size_t)NSB * C4_ * HW_];
__device__ float g_Q [(size_t)B_ * C_  * HW_];
__device__ float g_K [(size_t)B_ * C_  * HW_];

// ---------------------------------------------------------------------------
// Grouped 3x3 conv (groups=4, in=out=256ch), stride 1, pad 1.
// Processes BOTH sides (left=0, right=1) in one launch: z = s*8 + b*4 + g.
// MODE 1: input = BN(cat[side]) applied on load; output = leaky(conv + bias)
// MODE 2: input = t1[side] (raw); output = conv + bias + BN(cat[side]) residual
// Tile: 8 rows x 32 cols, 64 out channels per block. 256 threads,
// each thread computes 8 oc x 8 px. 2 blocks/SM forced.
// ---------------------------------------------------------------------------
constexpr int TH   = 8;
constexpr int TW   = 32;
constexpr int ICB  = 8;
constexpr int INROW   = TW + 2;   // 34 valid cols
constexpr int INPITCH = 35;       // padded pitch (conflict-free)

template <int MODE>
__global__ __launch_bounds__(256, 2)
void conv3x3_kernel(const float* __restrict__ catL,
                    const float* __restrict__ catR,
                    const float* __restrict__ tin,   // MODE2 input base (g_t1)
                    const float* __restrict__ wgt,   // (256, 64, 3, 3)
                    const float* __restrict__ bias,  // (256)
                    const float* __restrict__ bn_g,
                    const float* __restrict__ bn_b,
                    const float* __restrict__ bn_m,
                    const float* __restrict__ bn_v,
                    float* __restrict__ out)         // [sb][C4][HW]
{
    __shared__ float s_in[ICB * (TH + 2) * INPITCH];
    __shared__ float s_w[ICB * 64 * 9];
    __shared__ float s_sc[64];
    __shared__ float s_sh[64];

    const int tid = threadIdx.x;
    const int bz  = blockIdx.z;        // s*8 + b*4 + g
    const int s   = bz >> 3;
    const int b   = (bz >> 2) & 1;
    const int g   = bz & 3;
    const int sb  = s * B_ + b;
    const int y0  = blockIdx.y * TH;
    const int x0  = blockIdx.x * TW;
    const int chbase = g * 64;

    const float* cat = s ? catR : catL;

    if (tid < 64) {
        const int ch = chbase + tid;
        const float sc = bn_g[ch] * rsqrtf(bn_v[ch] + 1e-5f);
        s_sc[tid] = sc;
        s_sh[tid] = bn_b[ch] - bn_m[ch] * sc;
    }

    // thread mapping: og (out-channel octet), p -> (rowp, colp)
    const int og   = tid >> 5;        // 0..7
    const int p    = tid & 31;
    const int rowp = p >> 2;          // 0..7
    const int colp = (p & 3) * 8;     // 0,8,16,24

    float acc[8][8];
#pragma unroll
    for (int o = 0; o < 8; o++)
#pragma unroll
        for (int q = 0; q < 8; q++) acc[o][q] = 0.f;

    const float* inb = (MODE == 1)
        ? cat + (size_t)(b * C4_ + chbase) * HW_
        : tin + (size_t)(sb * C4_ + chbase) * HW_;

    __syncthreads();  // s_sc/s_sh ready

    for (int icb = 0; icb < 64; icb += ICB) {
        // stage input tile (with BN for MODE 1)
        for (int idx = tid; idx < ICB * (TH + 2) * INROW; idx += 256) {
            const int c   = idx / ((TH + 2) * INROW);
            const int rem = idx % ((TH + 2) * INROW);
            const int r   = rem / INROW;
            const int cc  = rem % INROW;
            const int gy  = y0 - 1 + r;
            const int gx  = x0 - 1 + cc;
            float v = 0.f;
            if ((unsigned)gy < (unsigned)H_ && (unsigned)gx < (unsigned)W_) {
                v = inb[(size_t)(icb + c) * HW_ + gy * W_ + gx];
                if (MODE == 1) v = v * s_sc[icb + c] + s_sh[icb + c];
            }
            s_in[(c * (TH + 2) + r) * INPITCH + cc] = v;
        }
        // stage weights: s_w[c*576 + oc*9 + t]
        for (int idx = tid; idx < ICB * 64 * 9; idx += 256) {
            const int c   = idx / 576;
            const int rem = idx % 576;
            const int oc  = rem / 9;
            const int t   = rem % 9;
            s_w[idx] = wgt[(size_t)(chbase + oc) * (64 * 9) + (icb + c) * 9 + t];
        }
        __syncthreads();

#pragma unroll 2
        for (int c = 0; c < ICB; c++) {
            float xv[3][10];
#pragma unroll
            for (int kh = 0; kh < 3; kh++)
#pragma unroll
                for (int t = 0; t < 10; t++)
                    xv[kh][t] = s_in[(c * (TH + 2) + rowp + kh) * INPITCH + colp + t];

#pragma unroll
            for (int o = 0; o < 8; o++) {
                const float* wp = &s_w[c * 576 + (og * 8 + o) * 9];
                const float w0 = wp[0], w1 = wp[1], w2 = wp[2];
                const float w3 = wp[3], w4 = wp[4], w5 = wp[5];
                const float w6 = wp[6], w7 = wp[7], w8 = wp[8];
#pragma unroll
                for (int q = 0; q < 8; q++) {
                    float sacc = acc[o][q];
                    sacc += w0 * xv[0][q] + w1 * xv[0][q + 1] + w2 * xv[0][q + 2];
                    sacc += w3 * xv[1][q] + w4 * xv[1][q + 1] + w5 * xv[1][q + 2];
                    sacc += w6 * xv[2][q] + w7 * xv[2][q + 1] + w8 * xv[2][q + 2];
                    acc[o][q] = sacc;
                }
            }
        }
        __syncthreads();
    }

    // epilogue
    const float* catb = cat + (size_t)(b * C4_ + chbase) * HW_;
    float*       outb = out + (size_t)(sb * C4_ + chbase) * HW_;
    const int y = y0 + rowp;
#pragma unroll
    for (int o = 0; o < 8; o++) {
        const int oc = og * 8 + o;
        const float bv = bias[chbase + oc];
#pragma unroll
        for (int q = 0; q < 8; q++) {
            const int x = x0 + colp + q;
            float v = acc[o][q] + bv;
            if (MODE == 1) {
                v = (v > 0.f) ? v : 0.1f * v;         // LeakyReLU(0.1)
            } else {
                const float cv = catb[(size_t)oc * HW_ + y * W_ + x];
                v += cv * s_sc[oc] + s_sh[oc];        // + BN(catfea) residual
            }
            outb[(size_t)oc * HW_ + y * W_ + x] = v;
        }
    }
}

// ---------------------------------------------------------------------------
// Grouped 1x1 conv: (64 out, 256 in, groups=4). Both sides in one launch:
// side 0 -> Q (bq weights), side 1 -> K (bs weights).
// ---------------------------------------------------------------------------
__global__ __launch_bounds__(256)
void conv1x1_kernel(const float* __restrict__ in,    // t2, [sb][256][HW]
                    const float* __restrict__ bqw, const float* __restrict__ bqb,
                    const float* __restrict__ bsw, const float* __restrict__ bsb,
                    float* __restrict__ Qb, float* __restrict__ Kb)
{
    const int idx = blockIdx.x * blockDim.x + threadIdx.x;
    if (idx >= 2 * B_ * C_ * HW_) return;
    const int s   = idx / (B_ * C_ * HW_);
    const int rem = idx - s * (B_ * C_ * HW_);
    const int pix = rem % HW_;
    const int o   = (rem / HW_) % C_;
    const int b   = rem / (C_ * HW_);
    const int gin = (o >> 4) * 64;   // group = o/16, input channels g*64..
    const float* ip = in + (size_t)((s * B_ + b) * C4_ + gin) * HW_ + pix;
    const float* wp = (s ? bsw : bqw) + o * 64;
    float accv = (s ? bsb : bqb)[o];
#pragma unroll 16
    for (int ic = 0; ic < 64; ic++)
        accv += __ldg(wp + ic) * __ldg(ip + (size_t)ic * HW_);
    (s ? Kb : Qb)[rem] = accv;
}

// ---------------------------------------------------------------------------
// Attention kernel. One block per (row i, batch b). 256 threads.
// Window centers per pixel from d_left/d_right; 8x8 windows; softmax over 64.
// Mean-subtraction of patches is dropped (softmax-invariant).
// ---------------------------------------------------------------------------
constexpr int WIN_F = 32 * 769;   // 32 ch chunk, 8 rows * 96 cols, pitch 769
constexpr int CEN_F = 32 * 96;
constexpr int M_F   = 96 * 65;    // 96 pixels x 64 taps, pitch 65
constexpr int SMEM_FLOATS = WIN_F + CEN_F + 2 * M_F + 6 * 96;
constexpr int SMEM_BYTES  = SMEM_FLOATS * 4;

__device__ __forceinline__
void load_win(const float* __restrict__ src, float* s_win, int b, int i, int c0, int tid)
{
    const float* sb = src + (size_t)(b * C_ + c0) * HW_;
    for (int idx = tid; idx < 32 * 768; idx += 256) {
        const int c   = idx / 768;
        const int rem = idx - c * 768;       // a*96 + col
        const int a   = rem / 96;
        const int col = rem - a * 96;
        const int gy  = i - 4 + a;
        float v = ((unsigned)gy < (unsigned)H_)
                      ? sb[(size_t)c * HW_ + gy * W_ + col] : 0.f;
        s_win[c * 769 + rem] = v;
    }
}

__device__ __forceinline__
void logits_pass(const float* __restrict__ winsrc, const float* __restrict__ censrc,
                 const int* s_ctr, float* Mtgt,
                 float* s_win, float* s_cen, int b, int i, int tid)
{
    for (int cb = 0; cb < 2; cb++) {
        const int c0 = cb * 32;
        load_win(winsrc, s_win, b, i, c0, tid);
        {
            const float* sb = censrc + (size_t)(b * C_ + c0) * HW_ + (size_t)i * W_;
            for (int idx = tid; idx < 32 * 96; idx += 256) {
                const int c = idx / 96, j = idx - c * 96;
                s_cen[c * 96 + j] = sb[(size_t)c * HW_ + j];
            }
        }
        __syncthreads();

        if (tid < 192) {
            const int j    = tid >> 1;
            const int koff = (tid & 1) * 32;
            const int cc   = s_ctr[j];
            float av[32];
#pragma unroll
            for (int kk = 0; kk < 32; kk++) av[kk] = 0.f;
            for (int c = 0; c < 32; c++) {
                const float qv = s_cen[c * 96 + j];
                const float* wb = s_win + c * 769;
#pragma unroll
                for (int kk = 0; kk < 32; kk++) {
                    const int k   = koff + kk;
                    const int a   = k >> 3;
                    const int dw  = k & 7;
                    const int col = cc - 4 + dw;
                    const float wv = ((unsigned)col < 96u) ? wb[a * 96 + col] : 0.f;
                    av[kk] += qv * wv;
                }
            }
            float* Mrow = Mtgt + j * 65 + koff;
#pragma unroll
            for (int kk = 0; kk < 32; kk++) Mrow[kk] += av[kk];
        }
        __syncthreads();
    }
}

__device__ __forceinline__
void softmax_row(float* row, int valid)
{
    if (!valid) {
#pragma unroll
        for (int k = 0; k < 64; k++) row[k] = 1.f / 64.f;
        return;
    }
    float mx = row[0];
#pragma unroll
    for (int k = 1; k < 64; k++) mx = fmaxf(mx, row[k]);
    float s = 0.f;
#pragma unroll
    for (int k = 0; k < 64; k++) { const float e = __expf(row[k] - mx); row[k] = e; s += e; }
    const float inv = 1.f / s;
#pragma unroll
    for (int k = 0; k < 64; k++) row[k] *= inv;
}

__device__ __forceinline__
void value_pass(const float* __restrict__ valsrc, const float* __restrict__ basesrc,
                float* __restrict__ outdst,
                const int* s_cr, const int* s_vR, const float* maskarr,
                const float* Mwt, float* s_win, int b, int i, int tid)
{
    for (int cb = 0; cb < 2; cb++) {
        const int c0 = cb * 32;
        load_win(valsrc, s_win, b, i, c0, tid);
        __syncthreads();

        const int clocal = tid & 31;
        const int jb     = tid >> 5;          // 0..7
        const float* wb  = s_win + clocal * 769;
        const int ch     = c0 + clocal;
        for (int m = 0; m < 12; m++) {
            const int j = jb + 8 * m;
            float accv = 0.f;
            if (s_vR[j]) {
                const int cc = s_cr[j];
                const float* Mrow = Mwt + j * 65;
#pragma unroll
                for (int k = 0; k < 64; k++) {
                    const int a   = k >> 3;
                    const int dw  = k & 7;
                    const int col = cc - 4 + dw;
                    const float wv = ((unsigned)col < 96u) ? wb[a * 96 + col] : 0.f;
                    accv += Mrow[k] * wv;
                }
            }
            const size_t gidx = ((size_t)(b * C_ + ch) * H_ + i) * W_ + j;
            outdst[gidx] = basesrc[gidx] + accv * maskarr[j];
        }
        __syncthreads();
    }
}

__global__ __launch_bounds__(256)
void attention_kernel(const float* __restrict__ Qf, const float* __restrict__ Kf,
                      const float* __restrict__ xL, const float* __restrict__ xR,
                      const int* __restrict__ dL, const int* __restrict__ dR,
                      float* __restrict__ outL, float* __restrict__ outR)
{
    extern __shared__ float smem[];
    float* s_win = smem;                         // WIN_F
    float* s_cen = s_win + WIN_F;                // CEN_F
    float* s_Mr  = s_cen + CEN_F;                // M_F
    float* s_Ml  = s_Mr + M_F;                   // M_F
    int*   s_cr  = (int*)(s_Ml + M_F);           // 96
    int*   s_cl  = s_cr + 96;                    // 96
    int*   s_vR  = s_cl + 96;                    // 96
    int*   s_vL  = s_vR + 96;                    // 96
    float* s_mL  = (float*)(s_vL + 96);          // 96 (V_left)
    float* s_mR  = s_mL + 96;                    // 96 (V_right)

    const int i = blockIdx.x;
    const int b = blockIdx.y;
    const int tid = threadIdx.x;

    if (tid < 96) {
        const int j = tid;
        const int dl = dL[(b * H_ + i) * W_ + j];
        const int dr = dR[(b * H_ + i) * W_ + j];
        const int cr = max(j - dl, 0);
        const int cl = min(j + dr, W_ - 1);
        s_cr[j] = cr;
        s_cl[j] = cl;
        const int rowok = (i + 4) < H_;
        s_vR[j] = (rowok && cr < W_ - 4) ? 1 : 0;
        s_vL[j] = (rowok && cl < W_ - 4) ? 1 : 0;
        s_mL[j] = (j - dl >= 0) ? 1.f : 0.f;
        s_mR[j] = (j + dr <= W_ - 1) ? 1.f : 0.f;
    }
    for (int idx = tid; idx < 2 * M_F; idx += 256) s_Mr[idx] = 0.f;
    __syncthreads();

    // logits r2l: window = K patches at cr, center = Q
    logits_pass(Kf, Qf, s_cr, s_Mr, s_win, s_cen, b, i, tid);
    // logits l2r: window = Q patches at cl, center = K
    logits_pass(Qf, Kf, s_cl, s_Ml, s_win, s_cen, b, i, tid);

    if (tid < 96) {
        softmax_row(s_Mr + tid * 65, s_vR[tid]);
        softmax_row(s_Ml + tid * 65, s_vL[tid]);
    }
    __syncthreads();

    // values (both use r2l coords, matching the source)
    value_pass(xR, xL, outL, s_cr, s_vR, s_mL, s_Mr, s_win, b, i, tid);
    value_pass(xL, xR, outR, s_cr, s_vR, s_mR, s_Ml, s_win, b, i, tid);
}

// ---------------------------------------------------------------------------
// Host launcher
// ---------------------------------------------------------------------------
extern "C" void kernel_launch(void* const* d_in, const int* in_sizes, int n_in,
                              void* d_out, int out_size)
{
    const float *xL, *xR, *catL, *catR;
    const float *bng, *bnb, *bnm, *bnv, *w1, *b1, *w2, *b2, *bqw, *bqb, *bsw, *bsb;
    const int *dL, *dR;

    const bool dict_order = (n_in >= 18) && (in_sizes[4] == B_ * H_ * W_);
    if (dict_order) {
        xL   = (const float*)d_in[0];  xR   = (const float*)d_in[1];
        catL = (const float*)d_in[2];  catR = (const float*)d_in[3];
        dL   = (const int*)  d_in[4];  dR   = (const int*)  d_in[5];
        bng  = (const float*)d_in[6];  bnb  = (const float*)d_in[7];
        bnm  = (const float*)d_in[8];  bnv  = (const float*)d_in[9];
        w1   = (const float*)d_in[10]; b1   = (const float*)d_in[11];
        w2   = (const float*)d_in[12]; b2   = (const float*)d_in[13];
        bqw  = (const float*)d_in[14]; bqb  = (const float*)d_in[15];
        bsw  = (const float*)d_in[16]; bsb  = (const float*)d_in[17];
    } else {
        xL   = (const float*)d_in[0];  xR   = (const float*)d_in[1];
        catL = (const float*)d_in[2];  catR = (const float*)d_in[3];
        bng  = (const float*)d_in[4];  bnb  = (const float*)d_in[5];
        bnm  = (const float*)d_in[6];  bnv  = (const float*)d_in[7];
        w1   = (const float*)d_in[8];  b1   = (const float*)d_in[9];
        w2   = (const float*)d_in[10]; b2   = (const float*)d_in[11];
        bqw  = (const float*)d_in[12]; bqb  = (const float*)d_in[13];
        bsw  = (const float*)d_in[14]; bsb  = (const float*)d_in[15];
        dL   = (const int*)  d_in[16]; dR   = (const int*)  d_in[17];
    }

    float *t1, *t2, *Qb, *Kb;
    cudaGetSymbolAddress((void**)&t1, g_t1);
    cudaGetSymbolAddress((void**)&t2, g_t2);
    cudaGetSymbolAddress((void**)&Qb, g_Q);
    cudaGetSymbolAddress((void**)&Kb, g_K);

    const dim3 cgrid(W_ / TW, H_ / TH, NSB * 4);   // (3, 8, 16) = 384 blocks
    const int n1x1 = 2 * B_ * C_ * HW_;

    // Both branches in one launch per conv layer
    conv3x3_kernel<1><<<cgrid, 256>>>(catL, catR, nullptr, w1, b1, bng, bnb, bnm, bnv, t1);
    conv3x3_kernel<2><<<cgrid, 256>>>(catL, catR, t1,      w2, b2, bng, bnb, bnm, bnv, t2);
    conv1x1_kernel<<<(n1x1 + 255) / 256, 256>>>(t2, bqw, bqb, bsw, bsb, Qb, Kb);

    // Attention + outputs
    cudaFuncSetAttribute(attention_kernel,
                         cudaFuncAttributeMaxDynamicSharedMemorySize, SMEM_BYTES);
    float* outL = (float*)d_out;
    float* outR = outL + (size_t)B_ * C_ * HW_;
    attention_kernel<<<dim3(H_, B_), 256, SMEM_BYTES>>>(Qb, Kb, xL, xR, dL, dR, outL, outR);
}

// round 4
// speedup vs baseline: 1.5136x; 1.0989x over previous
#include <cuda_runtime.h>
#include <cstddef>

// ---------------------------------------------------------------------------
// Problem constants
// ---------------------------------------------------------------------------
constexpr int B_  = 2;
constexpr int C_  = 64;
constexpr int C4_ = 256;
constexpr int H_  = 64;
constexpr int W_  = 96;
constexpr int HW_ = H_ * W_;
constexpr int NSB = 2 * B_;   // side * batch slots

typedef unsigned long long ull;

// Scratch (device globals: no allocations allowed). Layout [side*B+b][C4][HW]
__device__ float g_t1[(size_t)NSB * C4_ * HW_];
__device__ float g_t2[(size_t)NSB * C4_ * HW_];
__device__ float g_Q [(size_t)B_ * C_  * HW_];
__device__ float g_K [(size_t)B_ * C_  * HW_];

// ---------------------------------------------------------------------------
// f32x2 helpers (sm_100+ packed fp32 — exact, two independent IEEE FMAs)
// ---------------------------------------------------------------------------
__device__ __forceinline__ ull pk2(float a, float b) {
    ull r;
    asm("mov.b64 %0, {%1, %2};" : "=l"(r)
        : "r"(__float_as_uint(a)), "r"(__float_as_uint(b)));
    return r;
}
__device__ __forceinline__ void fma2(ull& d, ull a, ull b) {
    asm("fma.rn.f32x2 %0, %1, %2, %0;" : "+l"(d) : "l"(a), "l"(b));
}
__device__ __forceinline__ void unpk2(ull v, float& lo, float& hi) {
    unsigned l, h;
    asm("mov.b64 {%0, %1}, %2;" : "=r"(l), "=r"(h) : "l"(v));
    lo = __uint_as_float(l); hi = __uint_as_float(h);
}

// ---------------------------------------------------------------------------
// Grouped 3x3 conv (groups=4, in=out=256ch), stride 1, pad 1. Both sides in
// one launch: z = s*8 + b*4 + g.
// MODE 1: input = BN(cat[side]) on load; output = leaky(conv + bias)
// MODE 2: input = t1[side]; output = conv + bias + BN(cat[side]) residual
// Tile 8 rows x 32 cols x 64 oc per block; 256 threads; f32x2 math.
// ---------------------------------------------------------------------------
constexpr int TH   = 8;
constexpr int TW   = 32;
constexpr int ICB  = 8;
constexpr int INROW   = TW + 2;   // 34 valid cols
constexpr int INPITCH = 36;       // even pitch -> float2-aligned rows

constexpr int CONV_W2   = ICB * 9 * 64;            // ull count
constexpr int CONV_IN   = ICB * 10 * INPITCH;      // float count
constexpr int CONV_SMEM = CONV_W2 * 8 + CONV_IN * 4 + 2 * 64 * 4;

template <int MODE>
__global__ __launch_bounds__(256, 2)
void conv3x3_kernel(const float* __restrict__ catL,
                    const float* __restrict__ catR,
                    const float* __restrict__ tin,
                    const float* __restrict__ wgt,   // (256, 64, 3, 3)
                    const float* __restrict__ bias,  // (256)
                    const float* __restrict__ bn_g,
                    const float* __restrict__ bn_b,
                    const float* __restrict__ bn_m,
                    const float* __restrict__ bn_v,
                    float* __restrict__ out)
{
    extern __shared__ unsigned char csm[];
    ull*   s_w2 = (ull*)csm;                       // [oc*72 + c*9 + tap]
    float* s_in = (float*)(s_w2 + CONV_W2);        // [c][10][36]
    float* s_sc = s_in + CONV_IN;
    float* s_sh = s_sc + 64;

    const int tid = threadIdx.x;
    const int bz  = blockIdx.z;        // s*8 + b*4 + g
    const int s   = bz >> 3;
    const int b   = (bz >> 2) & 1;
    const int g   = bz & 3;
    const int sb  = s * B_ + b;
    const int y0  = blockIdx.y * TH;
    const int x0  = blockIdx.x * TW;
    const int chbase = g * 64;

    const float* cat = s ? catR : catL;

    if (tid < 64) {
        const int ch = chbase + tid;
        const float sc = bn_g[ch] * rsqrtf(bn_v[ch] + 1e-5f);
        s_sc[tid] = sc;
        s_sh[tid] = bn_b[ch] - bn_m[ch] * sc;
    }

    const int og   = tid >> 5;        // 0..7 (out-channel octet)
    const int p    = tid & 31;
    const int rowp = p >> 2;          // 0..7
    const int colp = (p & 3) * 8;     // 0,8,16,24

    ull acc2[8][4];
#pragma unroll
    for (int o = 0; o < 8; o++)
#pragma unroll
        for (int q = 0; q < 4; q++) acc2[o][q] = 0ULL;

    const float* inb = (MODE == 1)
        ? cat + (size_t)(b * C4_ + chbase) * HW_
        : tin + (size_t)(sb * C4_ + chbase) * HW_;

    __syncthreads();  // s_sc/s_sh ready

    for (int icb = 0; icb < 64; icb += ICB) {
        // stage input tile (BN on load for MODE 1)
        for (int idx = tid; idx < ICB * 10 * INROW; idx += 256) {
            const int c   = idx / (10 * INROW);
            const int rem = idx % (10 * INROW);
            const int r   = rem / INROW;
            const int cc  = rem % INROW;
            const int gy  = y0 - 1 + r;
            const int gx  = x0 - 1 + cc;
            float v = 0.f;
            if ((unsigned)gy < (unsigned)H_ && (unsigned)gx < (unsigned)W_) {
                v = inb[(size_t)(icb + c) * HW_ + gy * W_ + gx];
                if (MODE == 1) v = v * s_sc[icb + c] + s_sh[icb + c];
            }
            s_in[(c * 10 + r) * INPITCH + cc] = v;
        }
        // stage weights duplicated into f32x2: s_w2[oc*72 + c*9 + tap]
        for (int idx = tid; idx < ICB * 576; idx += 256) {
            const int oc  = idx / 72;
            const int r   = idx % 72;    // c*9 + tap
            const int c   = r / 9;
            const int tap = r % 9;
            const float w = wgt[(size_t)(chbase + oc) * 576 + (icb + c) * 9 + tap];
            s_w2[oc * 72 + r] = pk2(w, w);
        }
        __syncthreads();

#pragma unroll 2
        for (int c = 0; c < ICB; c++) {
            float xv[3][10];
#pragma unroll
            for (int kh = 0; kh < 3; kh++) {
                const float* rp = &s_in[(c * 10 + rowp + kh) * INPITCH + colp];
#pragma unroll
                for (int t5 = 0; t5 < 5; t5++) {
                    const float2 v = ((const float2*)rp)[t5];
                    xv[kh][2 * t5]     = v.x;
                    xv[kh][2 * t5 + 1] = v.y;
                }
            }
            const ull* wbase = &s_w2[(og * 8) * 72 + c * 9];
#pragma unroll
            for (int kh = 0; kh < 3; kh++) {
#pragma unroll
                for (int t = 0; t < 3; t++) {
                    const int tap = kh * 3 + t;
                    const ull xp0 = pk2(xv[kh][t],     xv[kh][t + 1]);
                    const ull xp1 = pk2(xv[kh][t + 2], xv[kh][t + 3]);
                    const ull xp2 = pk2(xv[kh][t + 4], xv[kh][t + 5]);
                    const ull xp3 = pk2(xv[kh][t + 6], xv[kh][t + 7]);
#pragma unroll
                    for (int o = 0; o < 8; o++) {
                        const ull w = wbase[o * 72 + tap];   // broadcast
                        fma2(acc2[o][0], w, xp0);
                        fma2(acc2[o][1], w, xp1);
                        fma2(acc2[o][2], w, xp2);
                        fma2(acc2[o][3], w, xp3);
                    }
                }
            }
        }
        __syncthreads();
    }

    // epilogue
    const float* catb = cat + (size_t)(b * C4_ + chbase) * HW_;
    float*       outb = out + (size_t)(sb * C4_ + chbase) * HW_;
    const int y = y0 + rowp;
#pragma unroll
    for (int o = 0; o < 8; o++) {
        const int oc = og * 8 + o;
        const float bv = bias[chbase + oc];
#pragma unroll
        for (int pq = 0; pq < 4; pq++) {
            float v0, v1;
            unpk2(acc2[o][pq], v0, v1);
#pragma unroll
            for (int half = 0; half < 2; half++) {
                const int x = x0 + colp + 2 * pq + half;
                float v = (half ? v1 : v0) + bv;
                if (MODE == 1) {
                    v = (v > 0.f) ? v : 0.1f * v;         // LeakyReLU(0.1)
                } else {
                    const float cv = catb[(size_t)oc * HW_ + y * W_ + x];
                    v += cv * s_sc[oc] + s_sh[oc];
                }
                outb[(size_t)oc * HW_ + y * W_ + x] = v;
            }
        }
    }
}

// ---------------------------------------------------------------------------
// Grouped 1x1 conv: 64oc <- 256ic, groups=4 (16oc per group reads 64ic).
// z = s*8 + b*4 + g. Each thread: 4 consecutive pixels, all 16 oc.
// ---------------------------------------------------------------------------
__global__ __launch_bounds__(256)
void conv1x1_kernel(const float* __restrict__ in,    // t2 [sb][256][HW]
                    const float* __restrict__ bqw, const float* __restrict__ bqb,
                    const float* __restrict__ bsw, const float* __restrict__ bsb,
                    float* __restrict__ Qb, float* __restrict__ Kb)
{
    __shared__ ull s_wt[16 * 64];   // duplicated weights, 8KB

    const int tid = threadIdx.x;
    const int bz  = blockIdx.z;
    const int s   = bz >> 3;
    const int b   = (bz >> 2) & 1;
    const int g   = bz & 3;

    const float* wsel = s ? bsw : bqw;
    const float* bsel = s ? bsb : bqb;

    for (int idx = tid; idx < 1024; idx += 256) {
        const int o  = idx >> 6;
        const int ic = idx & 63;
        const float w = wsel[(g * 16 + o) * 64 + ic];
        s_wt[idx] = pk2(w, w);
    }
    __syncthreads();

    const int px0 = blockIdx.x * 1024 + tid * 4;
    const float* ip = in + (size_t)((s * B_ + b) * C4_ + g * 64) * HW_ + px0;

    ull acc[16][2];
#pragma unroll
    for (int o = 0; o < 16; o++) {
        const float bv = bsel[g * 16 + o];
        acc[o][0] = pk2(bv, bv);
        acc[o][1] = pk2(bv, bv);
    }

    for (int ic = 0; ic < 64; ic++) {
        const float4 v = *(const float4*)&ip[(size_t)ic * HW_];
        const ull v01 = pk2(v.x, v.y);
        const ull v23 = pk2(v.z, v.w);
        const ull* wp = &s_wt[ic];
#pragma unroll
        for (int o = 0; o < 16; o++) {
            const ull w = wp[o * 64];   // broadcast
            fma2(acc[o][0], w, v01);
            fma2(acc[o][1], w, v23);
        }
    }

    float* op = (s ? Kb : Qb) + (size_t)(b * C_ + g * 16) * HW_ + px0;
#pragma unroll
    for (int o = 0; o < 16; o++) {
        float4 r;
        unpk2(acc[o][0], r.x, r.y);
        unpk2(acc[o][1], r.z, r.w);
        *(float4*)&op[(size_t)o * HW_] = r;
    }
}

// ---------------------------------------------------------------------------
// Attention kernel. Grid (H, B, dir). 256 threads, 2 blocks/SM.
// dir 0 = r2l (K-window/Q-center -> outL from xR)
// dir 1 = l2r (Q-window/K-center -> outR from xL, value coords still r2l).
// Window strips stored with 4-col zero padding -> no bounds predicates.
// Mean subtraction dropped (softmax-invariant).
// ---------------------------------------------------------------------------
constexpr int ROWP   = 105;             // window row pitch (96 + 4 pad each side, +1)
constexpr int CSTR   = 845;             // channel stride (8*105 + 5)
constexpr int WIN_F  = 16 * CSTR;       // 13520 floats
constexpr int CEN_F  = 16 * 96;         // 1536
constexpr int MPITCH = 66;
constexpr int M_F    = 96 * MPITCH;     // 6336
constexpr int OUT_F  = 16 * 96;         // 1536
constexpr int ATT_SMEM = (WIN_F + CEN_F + M_F + OUT_F) * 4 + 5 * 96 * 4;

__global__ __launch_bounds__(256, 2)
void attention_kernel(const float* __restrict__ Qf, const float* __restrict__ Kf,
                      const float* __restrict__ xL, const float* __restrict__ xR,
                      const int* __restrict__ dL, const int* __restrict__ dR,
                      float* __restrict__ outL, float* __restrict__ outR)
{
    extern __shared__ float smem[];
    float* s_win  = smem;                       // WIN_F
    float* s_cen  = s_win + WIN_F;              // CEN_F
    float* s_M    = s_cen + CEN_F;              // M_F
    float* s_out  = s_M + M_F;                  // OUT_F
    int*   s_cc   = (int*)(s_out + OUT_F);      // 96  logits centers (this dir)
    int*   s_cv   = s_cc + 96;                  // 96  value centers (= cr)
    int*   s_sval = s_cv + 96;                  // 96  softmax validity
    int*   s_vval = s_sval + 96;                // 96  value validity (= vR)
    float* s_mask = (float*)(s_vval + 96);      // 96  output mask

    const int i   = blockIdx.x;
    const int b   = blockIdx.y;
    const int z   = blockIdx.z;                 // 0=r2l, 1=l2r
    const int tid = threadIdx.x;

    if (tid < 96) {
        const int j  = tid;
        const int dl = dL[(b * H_ + i) * W_ + j];
        const int dr = dR[(b * H_ + i) * W_ + j];
        const int cr = max(j - dl, 0);
        const int cl = min(j + dr, W_ - 1);
        const int rowok = (i + 4) < H_;
        const int vR = (rowok && cr < W_ - 4) ? 1 : 0;
        const int vL = (rowok && cl < W_ - 4) ? 1 : 0;
        s_cc[j]   = z ? cl : cr;
        s_cv[j]   = cr;                         // value coords always r2l
        s_sval[j] = z ? vL : vR;
        s_vval[j] = vR;                         // value validity always vR
        s_mask[j] = z ? ((j + dr <= W_ - 1) ? 1.f : 0.f)
                      : ((j - dl >= 0)      ? 1.f : 0.f);
    }
    for (int idx = tid; idx < WIN_F; idx += 256) s_win[idx] = 0.f;  // incl. pads
    for (int idx = tid; idx < M_F;   idx += 256) s_M[idx]   = 0.f;
    __syncthreads();

    const float* winsrc = z ? Qf : Kf;
    const float* censrc = z ? Kf : Qf;
    const int aoff105 = (tid & 1) * 4 * ROWP;
    const int koff    = (tid & 1) * 32;
    const int jlog    = tid >> 1;

    // ---- logits ----
    for (int cb = 0; cb < 4; cb++) {
        const int c0 = cb * 16;
        const float* wsb = winsrc + (size_t)(b * C_ + c0) * HW_;
        for (int idx = tid; idx < 16 * 768; idx += 256) {
            const int c   = idx / 768;
            const int rem = idx - c * 768;      // a*96 + col
            const int a   = rem / 96;
            const int col = rem - a * 96;
            const int gy  = i - 4 + a;
            s_win[c * CSTR + a * ROWP + 4 + col] =
                ((unsigned)gy < (unsigned)H_)
                    ? wsb[(size_t)c * HW_ + gy * W_ + col] : 0.f;
        }
        const float* csb = censrc + (size_t)(b * C_ + c0) * HW_ + (size_t)i * W_;
        for (int idx = tid; idx < 16 * 96; idx += 256) {
            const int c = idx / 96, j = idx - c * 96;
            s_cen[idx] = csb[(size_t)c * HW_ + j];
        }
        __syncthreads();

        if (tid < 192) {
            const int cc = s_cc[jlog];
            float acc[32];
#pragma unroll
            for (int kk = 0; kk < 32; kk++) acc[kk] = 0.f;
            for (int c = 0; c < 16; c++) {
                const float qv = s_cen[c * 96 + jlog];
                const float* wb = s_win + c * CSTR + cc + aoff105;
#pragma unroll
                for (int kk = 0; kk < 32; kk++)
                    acc[kk] += qv * wb[(kk >> 3) * ROWP + (kk & 7)];
            }
            float* Mrow = s_M + jlog * MPITCH + koff;
#pragma unroll
            for (int kk = 0; kk < 32; kk++) Mrow[kk] += acc[kk];
        }
        __syncthreads();
    }

    // ---- softmax ----
    if (tid < 96) {
        float* row = s_M + tid * MPITCH;
        if (!s_sval[tid]) {
#pragma unroll
            for (int k = 0; k < 64; k++) row[k] = 1.f / 64.f;
        } else {
            float mx = row[0];
#pragma unroll
            for (int k = 1; k < 64; k++) mx = fmaxf(mx, row[k]);
            float ssum = 0.f;
#pragma unroll
            for (int k = 0; k < 64; k++) {
                const float e = __expf(row[k] - mx);
                row[k] = e; ssum += e;
            }
            const float inv = 1.f / ssum;
#pragma unroll
            for (int k = 0; k < 64; k++) row[k] *= inv;
        }
    }
    __syncthreads();

    // ---- value pass ----
    const float* valsrc  = z ? xL : xR;
    const float* basesrc = z ? xR : xL;
    float*       outdst  = z ? outR : outL;
    const int clocal = tid & 15;
    const int jb     = tid >> 4;

    for (int cb = 0; cb < 4; cb++) {
        const int c0 = cb * 16;
        const float* vsb = valsrc + (size_t)(b * C_ + c0) * HW_;
        for (int idx = tid; idx < 16 * 768; idx += 256) {
            const int c   = idx / 768;
            const int rem = idx - c * 768;
            const int a   = rem / 96;
            const int col = rem - a * 96;
            const int gy  = i - 4 + a;
            s_win[c * CSTR + a * ROWP + 4 + col] =
                ((unsigned)gy < (unsigned)H_)
                    ? vsb[(size_t)c * HW_ + gy * W_ + col] : 0.f;
        }
        __syncthreads();

        const float* wbase = s_win + clocal * CSTR;
#pragma unroll
        for (int m = 0; m < 6; m++) {
            const int j = jb + 16 * m;
            float acc = 0.f;
            if (s_vval[j]) {
                const float* wb   = wbase + s_cv[j];
                const float* Mrow = s_M + j * MPITCH;
#pragma unroll
                for (int kp = 0; kp < 32; kp++) {
                    const float2 mv = *(const float2*)(Mrow + 2 * kp);
                    const int k0 = 2 * kp, k1 = 2 * kp + 1;
                    acc += mv.x * wb[(k0 >> 3) * ROWP + (k0 & 7)];
                    acc += mv.y * wb[(k1 >> 3) * ROWP + (k1 & 7)];
                }
            }
            s_out[clocal * 96 + j] = acc * s_mask[j];
        }
        __syncthreads();

        for (int t = 0; t < 6; t++) {
            const int idx = tid + t * 256;
            const int c = idx / 96, j = idx - c * 96;
            const size_t gidx = ((size_t)(b * C_ + c0 + c) * H_ + i) * W_ + j;
            outdst[gidx] = basesrc[gidx] + s_out[idx];
        }
        __syncthreads();
    }
}

// ---------------------------------------------------------------------------
// Host launcher
// ---------------------------------------------------------------------------
extern "C" void kernel_launch(void* const* d_in, const int* in_sizes, int n_in,
                              void* d_out, int out_size)
{
    const float *xL, *xR, *catL, *catR;
    const float *bng, *bnb, *bnm, *bnv, *w1, *b1, *w2, *b2, *bqw, *bqb, *bsw, *bsb;
    const int *dL, *dR;

    const bool dict_order = (n_in >= 18) && (in_sizes[4] == B_ * H_ * W_);
    if (dict_order) {
        xL   = (const float*)d_in[0];  xR   = (const float*)d_in[1];
        catL = (const float*)d_in[2];  catR = (const float*)d_in[3];
        dL   = (const int*)  d_in[4];  dR   = (const int*)  d_in[5];
        bng  = (const float*)d_in[6];  bnb  = (const float*)d_in[7];
        bnm  = (const float*)d_in[8];  bnv  = (const float*)d_in[9];
        w1   = (const float*)d_in[10]; b1   = (const float*)d_in[11];
        w2   = (const float*)d_in[12]; b2   = (const float*)d_in[13];
        bqw  = (const float*)d_in[14]; bqb  = (const float*)d_in[15];
        bsw  = (const float*)d_in[16]; bsb  = (const float*)d_in[17];
    } else {
        xL   = (const float*)d_in[0];  xR   = (const float*)d_in[1];
        catL = (const float*)d_in[2];  catR = (const float*)d_in[3];
        bng  = (const float*)d_in[4];  bnb  = (const float*)d_in[5];
        bnm  = (const float*)d_in[6];  bnv  = (const float*)d_in[7];
        w1   = (const float*)d_in[8];  b1   = (const float*)d_in[9];
        w2   = (const float*)d_in[10]; b2   = (const float*)d_in[11];
        bqw  = (const float*)d_in[12]; bqb  = (const float*)d_in[13];
        bsw  = (const float*)d_in[14]; bsb  = (const float*)d_in[15];
        dL   = (const int*)  d_in[16]; dR   = (const int*)  d_in[17];
    }

    float *t1, *t2, *Qb, *Kb;
    cudaGetSymbolAddress((void**)&t1, g_t1);
    cudaGetSymbolAddress((void**)&t2, g_t2);
    cudaGetSymbolAddress((void**)&Qb, g_Q);
    cudaGetSymbolAddress((void**)&Kb, g_K);

    cudaFuncSetAttribute(conv3x3_kernel<1>,
                         cudaFuncAttributeMaxDynamicSharedMemorySize, CONV_SMEM);
    cudaFuncSetAttribute(conv3x3_kernel<2>,
                         cudaFuncAttributeMaxDynamicSharedMemorySize, CONV_SMEM);
    cudaFuncSetAttribute(attention_kernel,
                         cudaFuncAttributeMaxDynamicSharedMemorySize, ATT_SMEM);

    const dim3 cgrid(W_ / TW, H_ / TH, NSB * 4);   // (3, 8, 16) = 384 blocks

    conv3x3_kernel<1><<<cgrid, 256, CONV_SMEM>>>(catL, catR, nullptr, w1, b1,
                                                 bng, bnb, bnm, bnv, t1);
    conv3x3_kernel<2><<<cgrid, 256, CONV_SMEM>>>(catL, catR, t1, w2, b2,
                                                 bng, bnb, bnm, bnv, t2);
    conv1x1_kernel<<<dim3(6, 1, 16), 256>>>(t2, bqw, bqb, bsw, bsb, Qb, Kb);

    float* outL = (float*)d_out;
    float* outR = outL + (size_t)B_ * C_ * HW_;
    attention_kernel<<<dim3(H_, B_, 2), 256, ATT_SMEM>>>(Qb, Kb, xL, xR, dL, dR,
                                                         outL, outR);
}